// round 3
// baseline (speedup 1.0000x reference)
#include <cuda_runtime.h>
#include <math.h>

// Problem constants (match setup_inputs; runtime values read from in_sizes)
#define NMAXN 25000
#define EMAXE 400000
#define ETOTM (EMAXE + NMAXN)

// ---------------- scratch (device globals; no allocation allowed) ----------
__device__ float g_h0[NMAXN * 128];     // embed output
__device__ float g_h1[NMAXN * 512];     // layer1 pre-attention features [N,4,128]
__device__ float g_o1[NMAXN * 512];     // layer1 aggregated / post-ELU
__device__ float g_h2[NMAXN * 128];     // layer2 pre-attention features
__device__ float g_o2[NMAXN * 128];     // layer2 aggregated / post-ELU
__device__ float g_as1[NMAXN * 4], g_ad1[NMAXN * 4];
__device__ float g_m1[NMAXN * 4], g_s1[NMAXN * 4];
__device__ float g_ex1[ETOTM * 4];
__device__ float g_as2[NMAXN], g_ad2[NMAXN];
__device__ float g_m2[NMAXN], g_s2[NMAXN];
__device__ float g_ex2[ETOTM];
__device__ float g_pool[128];

// ---------------- helpers --------------------------------------------------
__device__ __forceinline__ void atomicMaxF(float* addr, float v) {
    if (v >= 0.0f) atomicMax((int*)addr, __float_as_int(v));
    else           atomicMin((unsigned int*)addr, __float_as_uint(v));
}

__global__ void fill_k(float* p, float v, int n) {
    int i = blockIdx.x * blockDim.x + threadIdx.x;
    if (i < n) p[i] = v;
}

// ---------------- SGEMM: C[M,N] = act(A[M,K] @ B[K,N] + bias) --------------
// 64x64 block tile, BK=16, 256 threads, 4x4 per-thread microtile.
// K must be a multiple of 16 (64/128/512 here), N a multiple of 64.
__global__ void sgemm64(const float* __restrict__ A, const float* __restrict__ B,
                        const float* __restrict__ bias, float* __restrict__ C,
                        int M, int N, int K, int act) {
    __shared__ float As[16][64];
    __shared__ float Bs[16][64 + 4];
    int tid = threadIdx.x;
    int tx = tid % 16, ty = tid / 16;
    int rowBase = blockIdx.y * 64, colBase = blockIdx.x * 64;

    float acc[4][4];
#pragma unroll
    for (int i = 0; i < 4; i++)
#pragma unroll
        for (int j = 0; j < 4; j++) acc[i][j] = 0.0f;

    for (int k0 = 0; k0 < K; k0 += 16) {
#pragma unroll
        for (int i = 0; i < 4; i++) {
            int lin = tid + i * 256;          // 0..1023
            int r = lin / 16, kk = lin % 16;  // A tile [64 rows][16 k]
            int gr = rowBase + r;
            As[kk][r] = (gr < M) ? A[(size_t)gr * K + k0 + kk] : 0.0f;
        }
#pragma unroll
        for (int i = 0; i < 4; i++) {
            int lin = tid + i * 256;
            int kk = lin / 64, c = lin % 64;  // B tile [16 k][64 cols]
            int gc = colBase + c;
            Bs[kk][c] = (gc < N) ? B[(size_t)(k0 + kk) * N + gc] : 0.0f;
        }
        __syncthreads();
#pragma unroll
        for (int kk = 0; kk < 16; kk++) {
            float a[4], b[4];
#pragma unroll
            for (int i = 0; i < 4; i++) a[i] = As[kk][ty * 4 + i];
#pragma unroll
            for (int j = 0; j < 4; j++) b[j] = Bs[kk][tx * 4 + j];
#pragma unroll
            for (int i = 0; i < 4; i++)
#pragma unroll
                for (int j = 0; j < 4; j++) acc[i][j] = fmaf(a[i], b[j], acc[i][j]);
        }
        __syncthreads();
    }

#pragma unroll
    for (int i = 0; i < 4; i++) {
        int r = rowBase + ty * 4 + i;
        if (r >= M) continue;
#pragma unroll
        for (int j = 0; j < 4; j++) {
            int c = colBase + tx * 4 + j;
            if (c >= N) continue;
            float v = acc[i][j];
            if (bias) v += bias[c];
            if (act == 1) v = fmaxf(v, 0.0f);
            C[(size_t)r * N + c] = v;
        }
    }
}

// ---------------- per-node attention logits: one warp per (node, head) -----
__global__ void alpha_k(const float* __restrict__ h, const float* __restrict__ asrc,
                        const float* __restrict__ adst,
                        float* __restrict__ outs, float* __restrict__ outd,
                        int N, int H, int C) {
    int w = (blockIdx.x * blockDim.x + threadIdx.x) >> 5;
    int lane = threadIdx.x & 31;
    if (w >= N * H) return;
    int hh = w % H;
    const float* hp = h + (size_t)w * C;
    const float* ap = asrc + hh * C;
    const float* bp = adst + hh * C;
    float s1 = 0.0f, s2 = 0.0f;
    for (int c = lane; c < C; c += 32) {
        float hv = hp[c];
        s1 = fmaf(hv, ap[c], s1);
        s2 = fmaf(hv, bp[c], s2);
    }
#pragma unroll
    for (int o = 16; o; o >>= 1) {
        s1 += __shfl_down_sync(0xffffffffu, s1, o);
        s2 += __shfl_down_sync(0xffffffffu, s2, o);
    }
    if (lane == 0) { outs[w] = s1; outd[w] = s2; }
}

// ---------------- edge passes ----------------------------------------------
// e index space: [0, E) real edges, [E, E+N) self loops. idx = e*H + h.
__global__ void edge_max_k(const int* __restrict__ src, const int* __restrict__ dst,
                           const float* __restrict__ as, const float* __restrict__ ad,
                           float* __restrict__ m, int E, int N, int H) {
    int total = (E + N) * H;
    int i = blockIdx.x * blockDim.x + threadIdx.x;
    if (i >= total) return;
    int e = i / H, h = i % H;
    int s = (e < E) ? src[e] : e - E;
    int d = (e < E) ? dst[e] : e - E;
    float v = as[s * H + h] + ad[d * H + h];
    v = (v >= 0.0f) ? v : 0.2f * v;
    atomicMaxF(&m[d * H + h], v);
}

__global__ void edge_exp_k(const int* __restrict__ src, const int* __restrict__ dst,
                           const float* __restrict__ as, const float* __restrict__ ad,
                           const float* __restrict__ m, float* __restrict__ ex,
                           float* __restrict__ ssum, int E, int N, int H) {
    int total = (E + N) * H;
    int i = blockIdx.x * blockDim.x + threadIdx.x;
    if (i >= total) return;
    int e = i / H, h = i % H;
    int s = (e < E) ? src[e] : e - E;
    int d = (e < E) ? dst[e] : e - E;
    float v = as[s * H + h] + ad[d * H + h];
    v = (v >= 0.0f) ? v : 0.2f * v;
    float x = __expf(v - m[d * H + h]);
    ex[i] = x;
    atomicAdd(&ssum[d * H + h], x);
}

__global__ void edge_norm_k(const int* __restrict__ dst, const float* __restrict__ ssum,
                            float* __restrict__ ex, int E, int N, int H) {
    int total = (E + N) * H;
    int i = blockIdx.x * blockDim.x + threadIdx.x;
    if (i >= total) return;
    int e = i / H, h = i % H;
    int d = (e < E) ? dst[e] : e - E;
    ex[i] = ex[i] / (ssum[d * H + h] + 1e-16f);
}

// scatter-add aggregation: thread per (edge, head, channel)
__global__ void edge_agg_k(const int* __restrict__ src, const int* __restrict__ dst,
                           const float* __restrict__ alpha, const float* __restrict__ h,
                           float* __restrict__ out, int E, int N, int H, int C) {
    int total = (E + N) * H * C;
    int i = blockIdx.x * blockDim.x + threadIdx.x;
    if (i >= total) return;
    int c = i % C;
    int t = i / C;
    int hh = t % H;
    int e = t / H;
    int s = (e < E) ? src[e] : e - E;
    int d = (e < E) ? dst[e] : e - E;
    float a = alpha[e * H + hh];
    atomicAdd(&out[((size_t)d * H + hh) * C + c], h[((size_t)s * H + hh) * C + c] * a);
}

__global__ void bias_elu_k(float* __restrict__ x, const float* __restrict__ bias,
                           int total, int F) {
    int i = blockIdx.x * blockDim.x + threadIdx.x;
    if (i >= total) return;
    float v = x[i] + bias[i % F];
    x[i] = (v > 0.0f) ? v : expm1f(v);
}

// ---------------- pooling + final linear -----------------------------------
__global__ void pool_k(const float* __restrict__ x, float* __restrict__ g, int N) {
    int c = threadIdx.x;  // 128
    float acc = 0.0f;
    for (int r = blockIdx.x; r < N; r += gridDim.x) acc += x[(size_t)r * 128 + c];
    atomicAdd(&g[c], acc);
}

__global__ void final_k(const float* __restrict__ g, const float* __restrict__ W,
                        const float* __restrict__ b, float* __restrict__ out,
                        int N, int K, int Nout) {
    __shared__ float gs[128];
    int t = threadIdx.x;  // 256
    if (t < K) gs[t] = g[t] / (float)N;
    __syncthreads();
    if (t < Nout) {
        float acc = b[t];
        for (int k = 0; k < K; k++) acc = fmaf(gs[k], W[k * Nout + t], acc);
        out[t] = acc;
    }
}

// ---------------- launch ----------------------------------------------------
static inline int cdiv(int a, int b) { return (a + b - 1) / b; }

extern "C" void kernel_launch(void* const* d_in, const int* in_sizes, int n_in,
                              void* d_out, int out_size) {
    const float* x     = (const float*)d_in[0];
    const int*   ei    = (const int*)d_in[1];
    const float* W_emb = (const float*)d_in[2];
    const float* b_emb = (const float*)d_in[3];
    const float* W1    = (const float*)d_in[4];
    const float* a1s   = (const float*)d_in[5];
    const float* a1d   = (const float*)d_in[6];
    const float* b1    = (const float*)d_in[7];
    const float* W2    = (const float*)d_in[8];
    const float* a2s   = (const float*)d_in[9];
    const float* a2d   = (const float*)d_in[10];
    const float* b2    = (const float*)d_in[11];
    const float* Wout  = (const float*)d_in[12];
    const float* bout  = (const float*)d_in[13];
    float* out = (float*)d_out;

    const int N = in_sizes[0] / 64;   // 25000
    const int E = in_sizes[1] / 2;    // 400000
    const int Etot = E + N;
    const int H1 = 4, C = 128, F1 = 512, OUTD = 256;
    const int* src = ei;
    const int* dst = ei + E;

    float *p_h0, *p_h1, *p_o1, *p_h2, *p_o2;
    float *p_as1, *p_ad1, *p_m1, *p_s1, *p_ex1;
    float *p_as2, *p_ad2, *p_m2, *p_s2, *p_ex2, *p_pool;
    cudaGetSymbolAddress((void**)&p_h0, g_h0);
    cudaGetSymbolAddress((void**)&p_h1, g_h1);
    cudaGetSymbolAddress((void**)&p_o1, g_o1);
    cudaGetSymbolAddress((void**)&p_h2, g_h2);
    cudaGetSymbolAddress((void**)&p_o2, g_o2);
    cudaGetSymbolAddress((void**)&p_as1, g_as1);
    cudaGetSymbolAddress((void**)&p_ad1, g_ad1);
    cudaGetSymbolAddress((void**)&p_m1, g_m1);
    cudaGetSymbolAddress((void**)&p_s1, g_s1);
    cudaGetSymbolAddress((void**)&p_ex1, g_ex1);
    cudaGetSymbolAddress((void**)&p_as2, g_as2);
    cudaGetSymbolAddress((void**)&p_ad2, g_ad2);
    cudaGetSymbolAddress((void**)&p_m2, g_m2);
    cudaGetSymbolAddress((void**)&p_s2, g_s2);
    cudaGetSymbolAddress((void**)&p_ex2, g_ex2);
    cudaGetSymbolAddress((void**)&p_pool, g_pool);

    const int TB = 256;

    // ---- init accumulators ----
    fill_k<<<cdiv(N * H1, TB), TB>>>(p_m1, -1e30f, N * H1);
    fill_k<<<cdiv(N * H1, TB), TB>>>(p_s1, 0.0f, N * H1);
    fill_k<<<cdiv(N * F1, TB), TB>>>(p_o1, 0.0f, N * F1);
    fill_k<<<cdiv(N, TB), TB>>>(p_m2, -1e30f, N);
    fill_k<<<cdiv(N, TB), TB>>>(p_s2, 0.0f, N);
    fill_k<<<cdiv(N * C, TB), TB>>>(p_o2, 0.0f, N * C);
    fill_k<<<1, 128>>>(p_pool, 0.0f, 128);

    // ---- embed: h0 = relu(x @ W_emb + b_emb)  [N,128] ----
    {
        dim3 grid(cdiv(128, 64), cdiv(N, 64));
        sgemm64<<<grid, 256>>>(x, W_emb, b_emb, p_h0, N, 128, 64, 1);
    }

    // ---- GAT layer 1 ----
    {
        dim3 grid(cdiv(F1, 64), cdiv(N, 64));
        sgemm64<<<grid, 256>>>(p_h0, W1, nullptr, p_h1, N, F1, 128, 0);
    }
    alpha_k<<<cdiv(N * H1 * 32, TB), TB>>>(p_h1, a1s, a1d, p_as1, p_ad1, N, H1, C);
    edge_max_k<<<cdiv(Etot * H1, TB), TB>>>(src, dst, p_as1, p_ad1, p_m1, E, N, H1);
    edge_exp_k<<<cdiv(Etot * H1, TB), TB>>>(src, dst, p_as1, p_ad1, p_m1, p_ex1, p_s1, E, N, H1);
    edge_norm_k<<<cdiv(Etot * H1, TB), TB>>>(dst, p_s1, p_ex1, E, N, H1);
    edge_agg_k<<<cdiv(Etot * H1 * C, TB), TB>>>(src, dst, p_ex1, p_h1, p_o1, E, N, H1, C);
    bias_elu_k<<<cdiv(N * F1, TB), TB>>>(p_o1, b1, N * F1, F1);

    // ---- GAT layer 2 (heads=1) ----
    {
        dim3 grid(cdiv(C, 64), cdiv(N, 64));
        sgemm64<<<grid, 256>>>(p_o1, W2, nullptr, p_h2, N, C, F1, 0);
    }
    alpha_k<<<cdiv(N * 32, TB), TB>>>(p_h2, a2s, a2d, p_as2, p_ad2, N, 1, C);
    edge_max_k<<<cdiv(Etot, TB), TB>>>(src, dst, p_as2, p_ad2, p_m2, E, N, 1);
    edge_exp_k<<<cdiv(Etot, TB), TB>>>(src, dst, p_as2, p_ad2, p_m2, p_ex2, p_s2, E, N, 1);
    edge_norm_k<<<cdiv(Etot, TB), TB>>>(dst, p_s2, p_ex2, E, N, 1);
    edge_agg_k<<<cdiv(Etot * C, TB), TB>>>(src, dst, p_ex2, p_h2, p_o2, E, N, 1, C);
    bias_elu_k<<<cdiv(N * C, TB), TB>>>(p_o2, b2, N * C, C);

    // ---- global mean pool + output linear ----
    pool_k<<<200, 128>>>(p_o2, p_pool, N);
    final_k<<<1, 256>>>(p_pool, Wout, bout, out, N, C, OUTD);
}

// round 7
// speedup vs baseline: 2.3657x; 2.3657x over previous
#include <cuda_runtime.h>
#include <math.h>

#define NMAXN 25000
#define EMAXE 400000
#define ETOTM (EMAXE + NMAXN)

// ---------------- scratch (device globals) ----------------------------------
__device__ float g_h0[NMAXN * 128];
__device__ float g_h1[NMAXN * 512];
__device__ float g_o1[NMAXN * 512];
__device__ float g_h2[NMAXN * 128];
__device__ float g_o2[NMAXN * 128];
__device__ float g_as1[NMAXN * 4], g_ad1[NMAXN * 4];
__device__ float g_m1[NMAXN * 4], g_s1[NMAXN * 4];
__device__ float g_ex1[ETOTM * 4];
__device__ float g_as2[NMAXN], g_ad2[NMAXN];
__device__ float g_m2[NMAXN], g_s2[NMAXN];
__device__ float g_ex2[ETOTM];
__device__ float g_pool[128];

// ---------------- helpers ----------------------------------------------------
__device__ __forceinline__ void atomicMaxF(float* addr, float v) {
    if (v >= 0.0f) atomicMax((int*)addr, __float_as_int(v));
    else           atomicMin((unsigned int*)addr, __float_as_uint(v));
}

__global__ void fill_k(float* p, float v, int n) {
    int i = blockIdx.x * blockDim.x + threadIdx.x;
    if (i < n) p[i] = v;
}

__global__ void fill4_k(float4* p, float v, int n4) {
    int i = blockIdx.x * blockDim.x + threadIdx.x;
    if (i < n4) p[i] = make_float4(v, v, v, v);
}

// ---------------- SGEMM: C[M,N] = act(A @ B + bias) -------------------------
// 128x128 block tile, BK=16, 256 threads, 8x8 microtile, float4 loads.
// Requires: K % 16 == 0, N % 128 == 0. M guarded.
__global__ __launch_bounds__(256) void sgemm128(
    const float* __restrict__ A, const float* __restrict__ B,
    const float* __restrict__ bias, float* __restrict__ C,
    int M, int N, int K, int act) {
    __shared__ float As[16][132];
    __shared__ float Bs[16][132];
    int tid = threadIdx.x;
    int tx = tid % 16, ty = tid / 16;
    int rowBase = blockIdx.y * 128, colBase = blockIdx.x * 128;

    float acc[8][8];
#pragma unroll
    for (int i = 0; i < 8; i++)
#pragma unroll
        for (int j = 0; j < 8; j++) acc[i][j] = 0.0f;

    for (int k0 = 0; k0 < K; k0 += 16) {
        // A tile: 128 rows x 16 k = 512 float4 (along K). 2 per thread.
#pragma unroll
        for (int i = 0; i < 2; i++) {
            int f = tid + i * 256;           // 0..511
            int r = f >> 2, kq = f & 3;      // row, k-quad
            int gr = rowBase + r;
            float4 v = make_float4(0.f, 0.f, 0.f, 0.f);
            if (gr < M) v = *(const float4*)(A + (size_t)gr * K + k0 + kq * 4);
            As[kq * 4 + 0][r] = v.x;
            As[kq * 4 + 1][r] = v.y;
            As[kq * 4 + 2][r] = v.z;
            As[kq * 4 + 3][r] = v.w;
        }
        // B tile: 16 k x 128 n = 512 float4 (along N). 2 per thread.
#pragma unroll
        for (int i = 0; i < 2; i++) {
            int f = tid + i * 256;
            int kk = f >> 5, nq = f & 31;
            float4 v = *(const float4*)(B + (size_t)(k0 + kk) * N + colBase + nq * 4);
            *(float4*)&Bs[kk][nq * 4] = v;
        }
        __syncthreads();
#pragma unroll
        for (int kk = 0; kk < 16; kk++) {
            float a[8], b[8];
#pragma unroll
            for (int i = 0; i < 4; i++) { a[i] = As[kk][ty * 8 + i]; a[i + 4] = As[kk][ty * 8 + 4 + i]; }
#pragma unroll
            for (int j = 0; j < 4; j++) { b[j] = Bs[kk][tx * 8 + j]; b[j + 4] = Bs[kk][tx * 8 + 4 + j]; }
#pragma unroll
            for (int i = 0; i < 8; i++)
#pragma unroll
                for (int j = 0; j < 8; j++) acc[i][j] = fmaf(a[i], b[j], acc[i][j]);
        }
        __syncthreads();
    }

#pragma unroll
    for (int i = 0; i < 8; i++) {
        int r = rowBase + ty * 8 + i;
        if (r >= M) continue;
#pragma unroll
        for (int jq = 0; jq < 2; jq++) {
            float4 v;
            int c = colBase + tx * 8 + jq * 4;
            v.x = acc[i][jq * 4 + 0]; v.y = acc[i][jq * 4 + 1];
            v.z = acc[i][jq * 4 + 2]; v.w = acc[i][jq * 4 + 3];
            if (bias) {
                v.x += bias[c + 0]; v.y += bias[c + 1];
                v.z += bias[c + 2]; v.w += bias[c + 3];
            }
            if (act == 1) {
                v.x = fmaxf(v.x, 0.f); v.y = fmaxf(v.y, 0.f);
                v.z = fmaxf(v.z, 0.f); v.w = fmaxf(v.w, 0.f);
            }
            *(float4*)(C + (size_t)r * N + c) = v;
        }
    }
}

// ---------------- per-node attention logits: one warp per (node, head) ------
__global__ void alpha_k(const float* __restrict__ h, const float* __restrict__ asrc,
                        const float* __restrict__ adst,
                        float* __restrict__ outs, float* __restrict__ outd,
                        int N, int H, int C) {
    int w = (blockIdx.x * blockDim.x + threadIdx.x) >> 5;
    int lane = threadIdx.x & 31;
    if (w >= N * H) return;
    int hh = w % H;
    const float4* hp = (const float4*)(h + (size_t)w * C);
    const float4* ap = (const float4*)(asrc + hh * C);
    const float4* bp = (const float4*)(adst + hh * C);
    float4 hv = hp[lane], av = ap[lane], bv = bp[lane];
    float s1 = hv.x * av.x + hv.y * av.y + hv.z * av.z + hv.w * av.w;
    float s2 = hv.x * bv.x + hv.y * bv.y + hv.z * bv.z + hv.w * bv.w;
#pragma unroll
    for (int o = 16; o; o >>= 1) {
        s1 += __shfl_down_sync(0xffffffffu, s1, o);
        s2 += __shfl_down_sync(0xffffffffu, s2, o);
    }
    if (lane == 0) { outs[w] = s1; outd[w] = s2; }
}

// ---------------- edge passes ------------------------------------------------
// pass 1: compute leaky logit, cache into ex[], atomic-max into m[]
__global__ void edge_max_k(const int* __restrict__ src, const int* __restrict__ dst,
                           const float* __restrict__ as, const float* __restrict__ ad,
                           float* __restrict__ m, float* __restrict__ ex,
                           int E, int N, int H) {
    int total = (E + N) * H;
    int i = blockIdx.x * blockDim.x + threadIdx.x;
    if (i >= total) return;
    int e = i / H, h = i - e * H;
    int s = (e < E) ? src[e] : e - E;
    int d = (e < E) ? dst[e] : e - E;
    float v = as[s * H + h] + ad[d * H + h];
    v = (v >= 0.0f) ? v : 0.2f * v;
    ex[i] = v;
    atomicMaxF(&m[d * H + h], v);
}

// pass 2: ex <- exp(logit - m[d]); atomic sum into ssum[d]
__global__ void edge_exp_k(const int* __restrict__ dst,
                           const float* __restrict__ m, float* __restrict__ ex,
                           float* __restrict__ ssum, int E, int N, int H) {
    int total = (E + N) * H;
    int i = blockIdx.x * blockDim.x + threadIdx.x;
    if (i >= total) return;
    int e = i / H, h = i - e * H;
    int d = (e < E) ? dst[e] : e - E;
    float x = __expf(ex[i] - m[d * H + h]);
    ex[i] = x;
    atomicAdd(&ssum[d * H + h], x);
}

// pass 3 (fused norm+agg): one warp per (edge, head); lane = 4 channels.
// C is fixed at 128 -> 32 lanes * float4.
__global__ void edge_agg_v4(const int* __restrict__ src, const int* __restrict__ dst,
                            const float* __restrict__ ex, const float* __restrict__ ssum,
                            const float* __restrict__ h, float* __restrict__ out,
                            int E, int N, int H) {
    int w = (blockIdx.x * blockDim.x + threadIdx.x) >> 5;
    int lane = threadIdx.x & 31;
    int total = (E + N) * H;
    if (w >= total) return;
    int e = w / H, hh = w - e * H;
    int s = (e < E) ? src[e] : e - E;
    int d = (e < E) ? dst[e] : e - E;
    float a = ex[w] / (ssum[d * H + hh] + 1e-16f);
    const float4* hp = (const float4*)(h + ((size_t)s * H + hh) * 128);
    float4* op = (float4*)(out + ((size_t)d * H + hh) * 128);
    float4 v = hp[lane];
    v.x *= a; v.y *= a; v.z *= a; v.w *= a;
    asm volatile("red.global.add.v4.f32 [%0], {%1, %2, %3, %4};"
                 :: "l"(op + lane), "f"(v.x), "f"(v.y), "f"(v.z), "f"(v.w)
                 : "memory");
}

__global__ void bias_elu_k(float* __restrict__ x, const float* __restrict__ bias,
                           int total, int F) {
    int i = blockIdx.x * blockDim.x + threadIdx.x;
    if (i >= total) return;
    float v = x[i] + bias[i % F];
    x[i] = (v > 0.0f) ? v : expm1f(v);
}

// ---------------- pooling + final linear ------------------------------------
__global__ void pool_k(const float* __restrict__ x, float* __restrict__ g, int N) {
    int c = threadIdx.x;  // 128
    float acc = 0.0f;
    for (int r = blockIdx.x; r < N; r += gridDim.x) acc += x[(size_t)r * 128 + c];
    atomicAdd(&g[c], acc);
}

__global__ void final_k(const float* __restrict__ g, const float* __restrict__ W,
                        const float* __restrict__ b, float* __restrict__ out,
                        int N, int K, int Nout) {
    __shared__ float gs[128];
    int t = threadIdx.x;  // 256
    if (t < K) gs[t] = g[t] / (float)N;
    __syncthreads();
    if (t < Nout) {
        float acc = b[t];
        for (int k = 0; k < K; k++) acc = fmaf(gs[k], W[k * Nout + t], acc);
        out[t] = acc;
    }
}

// ---------------- launch ------------------------------------------------------
static inline int cdiv(int a, int b) { return (a + b - 1) / b; }

extern "C" void kernel_launch(void* const* d_in, const int* in_sizes, int n_in,
                              void* d_out, int out_size) {
    const float* x     = (const float*)d_in[0];
    const int*   ei    = (const int*)d_in[1];
    const float* W_emb = (const float*)d_in[2];
    const float* b_emb = (const float*)d_in[3];
    const float* W1    = (const float*)d_in[4];
    const float* a1s   = (const float*)d_in[5];
    const float* a1d   = (const float*)d_in[6];
    const float* b1    = (const float*)d_in[7];
    const float* W2    = (const float*)d_in[8];
    const float* a2s   = (const float*)d_in[9];
    const float* a2d   = (const float*)d_in[10];
    const float* b2    = (const float*)d_in[11];
    const float* Wout  = (const float*)d_in[12];
    const float* bout  = (const float*)d_in[13];
    float* out = (float*)d_out;

    const int N = in_sizes[0] / 64;   // 25000
    const int E = in_sizes[1] / 2;    // 400000
    const int Etot = E + N;
    const int H1 = 4, C = 128, F1 = 512, OUTD = 256;
    const int* src = ei;
    const int* dst = ei + E;

    float *p_h0, *p_h1, *p_o1, *p_h2, *p_o2;
    float *p_as1, *p_ad1, *p_m1, *p_s1, *p_ex1;
    float *p_as2, *p_ad2, *p_m2, *p_s2, *p_ex2, *p_pool;
    cudaGetSymbolAddress((void**)&p_h0, g_h0);
    cudaGetSymbolAddress((void**)&p_h1, g_h1);
    cudaGetSymbolAddress((void**)&p_o1, g_o1);
    cudaGetSymbolAddress((void**)&p_h2, g_h2);
    cudaGetSymbolAddress((void**)&p_o2, g_o2);
    cudaGetSymbolAddress((void**)&p_as1, g_as1);
    cudaGetSymbolAddress((void**)&p_ad1, g_ad1);
    cudaGetSymbolAddress((void**)&p_m1, g_m1);
    cudaGetSymbolAddress((void**)&p_s1, g_s1);
    cudaGetSymbolAddress((void**)&p_ex1, g_ex1);
    cudaGetSymbolAddress((void**)&p_as2, g_as2);
    cudaGetSymbolAddress((void**)&p_ad2, g_ad2);
    cudaGetSymbolAddress((void**)&p_m2, g_m2);
    cudaGetSymbolAddress((void**)&p_s2, g_s2);
    cudaGetSymbolAddress((void**)&p_ex2, g_ex2);
    cudaGetSymbolAddress((void**)&p_pool, g_pool);

    const int TB = 256;

    // ---- init accumulators ----
    fill_k<<<cdiv(N * H1, TB), TB>>>(p_m1, -1e30f, N * H1);
    fill_k<<<cdiv(N * H1, TB), TB>>>(p_s1, 0.0f, N * H1);
    fill4_k<<<cdiv(N * F1 / 4, TB), TB>>>((float4*)p_o1, 0.0f, N * F1 / 4);
    fill_k<<<cdiv(N, TB), TB>>>(p_m2, -1e30f, N);
    fill_k<<<cdiv(N, TB), TB>>>(p_s2, 0.0f, N);
    fill4_k<<<cdiv(N * C / 4, TB), TB>>>((float4*)p_o2, 0.0f, N * C / 4);
    fill_k<<<1, 128>>>(p_pool, 0.0f, 128);

    // ---- embed: h0 = relu(x @ W_emb + b_emb)  [N,128] ----
    {
        dim3 grid(cdiv(128, 128), cdiv(N, 128));
        sgemm128<<<grid, 256>>>(x, W_emb, b_emb, p_h0, N, 128, 64, 1);
    }

    // ---- GAT layer 1 ----
    {
        dim3 grid(cdiv(F1, 128), cdiv(N, 128));
        sgemm128<<<grid, 256>>>(p_h0, W1, nullptr, p_h1, N, F1, 128, 0);
    }
    alpha_k<<<cdiv(N * H1 * 32, TB), TB>>>(p_h1, a1s, a1d, p_as1, p_ad1, N, H1, C);
    edge_max_k<<<cdiv(Etot * H1, TB), TB>>>(src, dst, p_as1, p_ad1, p_m1, p_ex1, E, N, H1);
    edge_exp_k<<<cdiv(Etot * H1, TB), TB>>>(dst, p_m1, p_ex1, p_s1, E, N, H1);
    edge_agg_v4<<<cdiv(Etot * H1 * 32, TB), TB>>>(src, dst, p_ex1, p_s1, p_h1, p_o1, E, N, H1);
    bias_elu_k<<<cdiv(N * F1, TB), TB>>>(p_o1, b1, N * F1, F1);

    // ---- GAT layer 2 (heads=1) ----
    {
        dim3 grid(cdiv(C, 128), cdiv(N, 128));
        sgemm128<<<grid, 256>>>(p_o1, W2, nullptr, p_h2, N, C, F1, 0);
    }
    alpha_k<<<cdiv(N * 32, TB), TB>>>(p_h2, a2s, a2d, p_as2, p_ad2, N, 1, C);
    edge_max_k<<<cdiv(Etot, TB), TB>>>(src, dst, p_as2, p_ad2, p_m2, p_ex2, E, N, 1);
    edge_exp_k<<<cdiv(Etot, TB), TB>>>(dst, p_m2, p_ex2, p_s2, E, N, 1);
    edge_agg_v4<<<cdiv(Etot * 32, TB), TB>>>(src, dst, p_ex2, p_s2, p_h2, p_o2, E, N, 1);
    bias_elu_k<<<cdiv(N * C, TB), TB>>>(p_o2, b2, N * C, C);

    // ---- global mean pool + output linear ----
    pool_k<<<200, 128>>>(p_o2, p_pool, N);
    final_k<<<1, 256>>>(p_pool, Wout, bout, out, N, C, OUTD);
}

// round 11
// speedup vs baseline: 2.5967x; 1.0976x over previous
#include <cuda_runtime.h>
#include <mma.h>
#include <math.h>

using namespace nvcuda;

#define NMAXN 25000
#define EMAXE 400000
#define ETOTM (EMAXE + NMAXN)

// ---------------- scratch (device globals) ----------------------------------
__device__ float g_h0[NMAXN * 128];
__device__ float g_h1[NMAXN * 512];
__device__ float g_o1[NMAXN * 512];
__device__ float g_h2[NMAXN * 128];
__device__ float g_o2[NMAXN * 128];
__device__ float g_as1[NMAXN * 4], g_ad1[NMAXN * 4];
__device__ float g_m1[NMAXN * 4], g_s1[NMAXN * 4];
__device__ float g_ex1[ETOTM * 4];
__device__ float g_as2[NMAXN], g_ad2[NMAXN];
__device__ float g_m2[NMAXN], g_s2[NMAXN];
__device__ float g_ex2[ETOTM];
__device__ float g_pool[128];

// ---------------- helpers ----------------------------------------------------
__device__ __forceinline__ void atomicMaxF(float* addr, float v) {
    if (v >= 0.0f) atomicMax((int*)addr, __float_as_int(v));
    else           atomicMin((unsigned int*)addr, __float_as_uint(v));
}

__global__ void fill_k(float* p, float v, int n) {
    int i = blockIdx.x * blockDim.x + threadIdx.x;
    if (i < n) p[i] = v;
}

// ---------------- TF32 tensor-core GEMM -------------------------------------
// C[M,N] = act(A[M,K] @ B[K,N] + bias). 128x128 block tile, BK=32.
// 8 warps: 4x2 layout, warp tile 32x64 = 2x4 wmma m16n16k8 fragments.
// Requires: K % 32 == 0, N % 128 == 0. M guarded.
#define AS_STRIDE 36
#define BS_STRIDE 132
#define AS_FLOATS (128 * AS_STRIDE)

__global__ __launch_bounds__(256) void gemm_tf32(
    const float* __restrict__ A, const float* __restrict__ B,
    const float* __restrict__ bias, float* __restrict__ C,
    int M, int N, int K, int act) {
    __shared__ float smem[AS_FLOATS + 32 * BS_STRIDE];  // ~35 KB
    float* As = smem;                 // [128][36]
    float* Bs = smem + AS_FLOATS;     // [32][132]

    int tid = threadIdx.x;
    int lane = tid & 31;
    int wid = tid >> 5;
    int wr = wid >> 1;   // 0..3
    int wc = wid & 1;    // 0..1
    int rowBase = blockIdx.y * 128, colBase = blockIdx.x * 128;

    wmma::fragment<wmma::accumulator, 16, 16, 8, float> acc[2][4];
#pragma unroll
    for (int i = 0; i < 2; i++)
#pragma unroll
        for (int j = 0; j < 4; j++) wmma::fill_fragment(acc[i][j], 0.0f);

    for (int k0 = 0; k0 < K; k0 += 32) {
        // A tile: 128 rows x 32 k = 1024 float4, 4 per thread
#pragma unroll
        for (int i = 0; i < 4; i++) {
            int f = tid + i * 256;
            int r = f >> 3, kq = f & 7;
            int gr = rowBase + r;
            float4 v = make_float4(0.f, 0.f, 0.f, 0.f);
            if (gr < M) v = *(const float4*)(A + (size_t)gr * K + k0 + kq * 4);
            float* p = As + r * AS_STRIDE + kq * 4;
            p[0] = wmma::__float_to_tf32(v.x);
            p[1] = wmma::__float_to_tf32(v.y);
            p[2] = wmma::__float_to_tf32(v.z);
            p[3] = wmma::__float_to_tf32(v.w);
        }
        // B tile: 32 k x 128 n = 1024 float4, 4 per thread
#pragma unroll
        for (int i = 0; i < 4; i++) {
            int f = tid + i * 256;
            int kk = f >> 5, nq = f & 31;
            float4 v = *(const float4*)(B + (size_t)(k0 + kk) * N + colBase + nq * 4);
            float* p = Bs + kk * BS_STRIDE + nq * 4;
            p[0] = wmma::__float_to_tf32(v.x);
            p[1] = wmma::__float_to_tf32(v.y);
            p[2] = wmma::__float_to_tf32(v.z);
            p[3] = wmma::__float_to_tf32(v.w);
        }
        __syncthreads();
#pragma unroll
        for (int ks = 0; ks < 32; ks += 8) {
            wmma::fragment<wmma::matrix_a, 16, 16, 8, wmma::precision::tf32, wmma::row_major> fa[2];
            wmma::fragment<wmma::matrix_b, 16, 16, 8, wmma::precision::tf32, wmma::row_major> fb[4];
#pragma unroll
            for (int i = 0; i < 2; i++)
                wmma::load_matrix_sync(fa[i], As + (wr * 32 + i * 16) * AS_STRIDE + ks, AS_STRIDE);
#pragma unroll
            for (int j = 0; j < 4; j++)
                wmma::load_matrix_sync(fb[j], Bs + ks * BS_STRIDE + wc * 64 + j * 16, BS_STRIDE);
#pragma unroll
            for (int i = 0; i < 2; i++)
#pragma unroll
                for (int j = 0; j < 4; j++)
                    wmma::mma_sync(acc[i][j], fa[i], fb[j], acc[i][j]);
        }
        __syncthreads();
    }

    // epilogue: per-warp 16x16 staging (reuses smem; all compute done)
    float* wepi = smem + wid * 256;
#pragma unroll
    for (int i = 0; i < 2; i++) {
#pragma unroll
        for (int j = 0; j < 4; j++) {
            wmma::store_matrix_sync(wepi, acc[i][j], 16, wmma::mem_row_major);
            __syncwarp();
            int r0 = rowBase + wr * 32 + i * 16;
            int c0 = colBase + wc * 64 + j * 16;
#pragma unroll
            for (int t = lane; t < 256; t += 32) {
                int rr = t >> 4, cc = t & 15;
                int r = r0 + rr;
                if (r < M) {
                    float v = wepi[t];
                    int c = c0 + cc;
                    if (bias) v += bias[c];
                    if (act == 1) v = fmaxf(v, 0.0f);
                    C[(size_t)r * N + c] = v;
                }
            }
            __syncwarp();
        }
    }
}

// ---------------- per-node attention logits: one warp per (node, head) ------
__global__ void alpha_k(const float* __restrict__ h, const float* __restrict__ asrc,
                        const float* __restrict__ adst,
                        float* __restrict__ outs, float* __restrict__ outd,
                        int N, int H, int C) {
    int w = (blockIdx.x * blockDim.x + threadIdx.x) >> 5;
    int lane = threadIdx.x & 31;
    if (w >= N * H) return;
    int hh = w % H;
    const float4* hp = (const float4*)(h + (size_t)w * C);
    const float4* ap = (const float4*)(asrc + hh * C);
    const float4* bp = (const float4*)(adst + hh * C);
    float4 hv = hp[lane], av = ap[lane], bv = bp[lane];
    float s1 = hv.x * av.x + hv.y * av.y + hv.z * av.z + hv.w * av.w;
    float s2 = hv.x * bv.x + hv.y * bv.y + hv.z * bv.z + hv.w * bv.w;
#pragma unroll
    for (int o = 16; o; o >>= 1) {
        s1 += __shfl_down_sync(0xffffffffu, s1, o);
        s2 += __shfl_down_sync(0xffffffffu, s2, o);
    }
    if (lane == 0) { outs[w] = s1; outd[w] = s2; }
}

// ---------------- edge passes ------------------------------------------------
__device__ __forceinline__ float leaky(float v) { return (v >= 0.0f) ? v : 0.2f * v; }

// H=4 vectorized: one thread per edge handles all 4 heads.
__global__ void edge_max4_k(const int* __restrict__ src, const int* __restrict__ dst,
                            const float4* __restrict__ as, const float4* __restrict__ ad,
                            float* __restrict__ m, float4* __restrict__ ex, int E, int N) {
    int e = blockIdx.x * blockDim.x + threadIdx.x;
    if (e >= E + N) return;
    int s = (e < E) ? src[e] : e - E;
    int d = (e < E) ? dst[e] : e - E;
    float4 a = as[s], b = ad[d];
    float4 v;
    v.x = leaky(a.x + b.x); v.y = leaky(a.y + b.y);
    v.z = leaky(a.z + b.z); v.w = leaky(a.w + b.w);
    ex[e] = v;
    atomicMaxF(&m[d * 4 + 0], v.x);
    atomicMaxF(&m[d * 4 + 1], v.y);
    atomicMaxF(&m[d * 4 + 2], v.z);
    atomicMaxF(&m[d * 4 + 3], v.w);
}

__global__ void edge_exp4_k(const int* __restrict__ dst, const float4* __restrict__ m,
                            float4* __restrict__ ex, float* __restrict__ ssum, int E, int N) {
    int e = blockIdx.x * blockDim.x + threadIdx.x;
    if (e >= E + N) return;
    int d = (e < E) ? dst[e] : e - E;
    float4 mm = m[d];
    float4 v = ex[e];
    v.x = __expf(v.x - mm.x); v.y = __expf(v.y - mm.y);
    v.z = __expf(v.z - mm.z); v.w = __expf(v.w - mm.w);
    ex[e] = v;
    atomicAdd(&ssum[d * 4 + 0], v.x);
    atomicAdd(&ssum[d * 4 + 1], v.y);
    atomicAdd(&ssum[d * 4 + 2], v.z);
    atomicAdd(&ssum[d * 4 + 3], v.w);
}

// H=1 scalar variants
__global__ void edge_max_k(const int* __restrict__ src, const int* __restrict__ dst,
                           const float* __restrict__ as, const float* __restrict__ ad,
                           float* __restrict__ m, float* __restrict__ ex, int E, int N) {
    int e = blockIdx.x * blockDim.x + threadIdx.x;
    if (e >= E + N) return;
    int s = (e < E) ? src[e] : e - E;
    int d = (e < E) ? dst[e] : e - E;
    float v = leaky(as[s] + ad[d]);
    ex[e] = v;
    atomicMaxF(&m[d], v);
}

__global__ void edge_exp_k(const int* __restrict__ dst, const float* __restrict__ m,
                           float* __restrict__ ex, float* __restrict__ ssum, int E, int N) {
    int e = blockIdx.x * blockDim.x + threadIdx.x;
    if (e >= E + N) return;
    int d = (e < E) ? dst[e] : e - E;
    float x = __expf(ex[e] - m[d]);
    ex[e] = x;
    atomicAdd(&ssum[d], x);
}

// fused norm+agg: one warp per (edge, head); lane = 4 channels (C=128).
__global__ void edge_agg_v4(const int* __restrict__ src, const int* __restrict__ dst,
                            const float* __restrict__ ex, const float* __restrict__ ssum,
                            const float* __restrict__ h, float* __restrict__ out,
                            int E, int N, int H) {
    int w = (blockIdx.x * blockDim.x + threadIdx.x) >> 5;
    int lane = threadIdx.x & 31;
    int total = (E + N) * H;
    if (w >= total) return;
    int e = w / H, hh = w - e * H;
    int s = (e < E) ? src[e] : e - E;
    int d = (e < E) ? dst[e] : e - E;
    float a = ex[w] / (ssum[d * H + hh] + 1e-16f);
    const float4* hp = (const float4*)(h + ((size_t)s * H + hh) * 128);
    float4* op = (float4*)(out + ((size_t)d * H + hh) * 128);
    float4 v = hp[lane];
    v.x *= a; v.y *= a; v.z *= a; v.w *= a;
    asm volatile("red.global.add.v4.f32 [%0], {%1, %2, %3, %4};"
                 :: "l"(op + lane), "f"(v.x), "f"(v.y), "f"(v.z), "f"(v.w)
                 : "memory");
}

__global__ void bias_elu_k(float* __restrict__ x, const float* __restrict__ bias,
                           int total, int F) {
    int i = blockIdx.x * blockDim.x + threadIdx.x;
    if (i >= total) return;
    float v = x[i] + bias[i % F];
    x[i] = (v > 0.0f) ? v : expm1f(v);
}

// ---------------- pooling + final linear ------------------------------------
__global__ void pool_k(const float* __restrict__ x, float* __restrict__ g, int N) {
    int c = threadIdx.x;  // 128
    float acc = 0.0f;
    for (int r = blockIdx.x; r < N; r += gridDim.x) acc += x[(size_t)r * 128 + c];
    atomicAdd(&g[c], acc);
}

__global__ void final_k(const float* __restrict__ g, const float* __restrict__ W,
                        const float* __restrict__ b, float* __restrict__ out,
                        int N, int K, int Nout) {
    __shared__ float gs[128];
    int t = threadIdx.x;  // 256
    if (t < K) gs[t] = g[t] / (float)N;
    __syncthreads();
    if (t < Nout) {
        float acc = b[t];
        for (int k = 0; k < K; k++) acc = fmaf(gs[k], W[k * Nout + t], acc);
        out[t] = acc;
    }
}

// ---------------- launch ------------------------------------------------------
static inline int cdiv(int a, int b) { return (a + b - 1) / b; }

extern "C" void kernel_launch(void* const* d_in, const int* in_sizes, int n_in,
                              void* d_out, int out_size) {
    const float* x     = (const float*)d_in[0];
    const int*   ei    = (const int*)d_in[1];
    const float* W_emb = (const float*)d_in[2];
    const float* b_emb = (const float*)d_in[3];
    const float* W1    = (const float*)d_in[4];
    const float* a1s   = (const float*)d_in[5];
    const float* a1d   = (const float*)d_in[6];
    const float* b1    = (const float*)d_in[7];
    const float* W2    = (const float*)d_in[8];
    const float* a2s   = (const float*)d_in[9];
    const float* a2d   = (const float*)d_in[10];
    const float* b2    = (const float*)d_in[11];
    const float* Wout  = (const float*)d_in[12];
    const float* bout  = (const float*)d_in[13];
    float* out = (float*)d_out;

    const int N = in_sizes[0] / 64;   // 25000
    const int E = in_sizes[1] / 2;    // 400000
    const int Etot = E + N;
    const int H1 = 4, C = 128, F1 = 512, OUTD = 256;
    const int* src = ei;
    const int* dst = ei + E;

    float *p_h0, *p_h1, *p_o1, *p_h2, *p_o2;
    float *p_as1, *p_ad1, *p_m1, *p_s1, *p_ex1;
    float *p_as2, *p_ad2, *p_m2, *p_s2, *p_ex2, *p_pool;
    cudaGetSymbolAddress((void**)&p_h0, g_h0);
    cudaGetSymbolAddress((void**)&p_h1, g_h1);
    cudaGetSymbolAddress((void**)&p_o1, g_o1);
    cudaGetSymbolAddress((void**)&p_h2, g_h2);
    cudaGetSymbolAddress((void**)&p_o2, g_o2);
    cudaGetSymbolAddress((void**)&p_as1, g_as1);
    cudaGetSymbolAddress((void**)&p_ad1, g_ad1);
    cudaGetSymbolAddress((void**)&p_m1, g_m1);
    cudaGetSymbolAddress((void**)&p_s1, g_s1);
    cudaGetSymbolAddress((void**)&p_ex1, g_ex1);
    cudaGetSymbolAddress((void**)&p_as2, g_as2);
    cudaGetSymbolAddress((void**)&p_ad2, g_ad2);
    cudaGetSymbolAddress((void**)&p_m2, g_m2);
    cudaGetSymbolAddress((void**)&p_s2, g_s2);
    cudaGetSymbolAddress((void**)&p_ex2, g_ex2);
    cudaGetSymbolAddress((void**)&p_pool, g_pool);

    const int TB = 256;

    // ---- init accumulators (zero fills via memset; -1e30 fills via kernel) --
    fill_k<<<cdiv(N * H1, TB), TB>>>(p_m1, -1e30f, N * H1);
    fill_k<<<cdiv(N, TB), TB>>>(p_m2, -1e30f, N);
    cudaMemsetAsync(p_s1, 0, (size_t)N * H1 * sizeof(float));
    cudaMemsetAsync(p_o1, 0, (size_t)N * F1 * sizeof(float));
    cudaMemsetAsync(p_s2, 0, (size_t)N * sizeof(float));
    cudaMemsetAsync(p_o2, 0, (size_t)N * C * sizeof(float));
    cudaMemsetAsync(p_pool, 0, 128 * sizeof(float));

    // ---- embed: h0 = relu(x @ W_emb + b_emb)  [N,128] ----
    {
        dim3 grid(1, cdiv(N, 128));
        gemm_tf32<<<grid, 256>>>(x, W_emb, b_emb, p_h0, N, 128, 64, 1);
    }

    // ---- GAT layer 1 ----
    {
        dim3 grid(cdiv(F1, 128), cdiv(N, 128));
        gemm_tf32<<<grid, 256>>>(p_h0, W1, nullptr, p_h1, N, F1, 128, 0);
    }
    alpha_k<<<cdiv(N * H1 * 32, TB), TB>>>(p_h1, a1s, a1d, p_as1, p_ad1, N, H1, C);
    edge_max4_k<<<cdiv(Etot, TB), TB>>>(src, dst, (const float4*)p_as1, (const float4*)p_ad1,
                                        p_m1, (float4*)p_ex1, E, N);
    edge_exp4_k<<<cdiv(Etot, TB), TB>>>(dst, (const float4*)p_m1, (float4*)p_ex1, p_s1, E, N);
    edge_agg_v4<<<cdiv(Etot * H1 * 32, TB), TB>>>(src, dst, p_ex1, p_s1, p_h1, p_o1, E, N, H1);
    bias_elu_k<<<cdiv(N * F1, TB), TB>>>(p_o1, b1, N * F1, F1);

    // ---- GAT layer 2 (heads=1) ----
    {
        dim3 grid(1, cdiv(N, 128));
        gemm_tf32<<<grid, 256>>>(p_o1, W2, nullptr, p_h2, N, C, F1, 0);
    }
    alpha_k<<<cdiv(N * 32, TB), TB>>>(p_h2, a2s, a2d, p_as2, p_ad2, N, 1, C);
    edge_max_k<<<cdiv(Etot, TB), TB>>>(src, dst, p_as2, p_ad2, p_m2, p_ex2, E, N);
    edge_exp_k<<<cdiv(Etot, TB), TB>>>(dst, p_m2, p_ex2, p_s2, E, N);
    edge_agg_v4<<<cdiv(Etot * 32, TB), TB>>>(src, dst, p_ex2, p_s2, p_h2, p_o2, E, N, 1);
    bias_elu_k<<<cdiv(N * C, TB), TB>>>(p_o2, b2, N * C, C);

    // ---- global mean pool + output linear ----
    pool_k<<<200, 128>>>(p_o2, p_pool, N);
    final_k<<<1, 256>>>(p_pool, Wout, bout, out, N, C, OUTD);
}

// round 16
// speedup vs baseline: 4.6512x; 1.7912x over previous
#include <cuda_runtime.h>
#include <mma.h>
#include <math.h>

using namespace nvcuda;

#define NMAXN 25000
#define EMAXE 400000

// ---------------- scratch (device globals) ----------------------------------
__device__ float g_h0[NMAXN * 128];
__device__ float g_h1[NMAXN * 512];
__device__ float g_o1[NMAXN * 512];
__device__ float g_h2[NMAXN * 128];
__device__ float g_o2[NMAXN * 128];
__device__ float g_as1[NMAXN * 4], g_ad1[NMAXN * 4];
__device__ float g_as2[NMAXN], g_ad2[NMAXN];
__device__ float g_pool[128];
// CSR scratch
__device__ int g_deg[NMAXN];
__device__ int g_excl[NMAXN];
__device__ int g_rowptr[NMAXN + 1];
__device__ int g_cursor[NMAXN];
__device__ int g_csrc[EMAXE];
__device__ int g_bsums[64];

// ---------------- CSR build --------------------------------------------------
__global__ void hist_k(const int* __restrict__ dst, int* __restrict__ deg, int E) {
    int e = blockIdx.x * blockDim.x + threadIdx.x;
    if (e < E) atomicAdd(&deg[dst[e]], 1);
}

// per-1024-block exclusive scan (Hillis-Steele on inclusive, minus self)
__global__ void scan1_k(const int* __restrict__ deg, int* __restrict__ excl,
                        int* __restrict__ bsums, int n) {
    __shared__ int sh[1024];
    int i = blockIdx.x * 1024 + threadIdx.x;
    int v = (i < n) ? deg[i] : 0;
    sh[threadIdx.x] = v;
    __syncthreads();
    for (int off = 1; off < 1024; off <<= 1) {
        int t = (threadIdx.x >= off) ? sh[threadIdx.x - off] : 0;
        __syncthreads();
        sh[threadIdx.x] += t;
        __syncthreads();
    }
    if (i < n) excl[i] = sh[threadIdx.x] - v;
    if (threadIdx.x == 1023) bsums[blockIdx.x] = sh[1023];
}

__global__ void scan2_k(int* bsums, int nb) {
    if (threadIdx.x == 0 && blockIdx.x == 0) {
        int acc = 0;
        for (int i = 0; i < nb; i++) { int t = bsums[i]; bsums[i] = acc; acc += t; }
    }
}

__global__ void scan3_k(const int* __restrict__ excl, const int* __restrict__ bsums,
                        int* __restrict__ rowptr, int* __restrict__ cursor, int n, int E) {
    int i = blockIdx.x * blockDim.x + threadIdx.x;
    if (i < n) {
        int v = excl[i] + bsums[i >> 10];
        rowptr[i] = v;
        cursor[i] = v;
    }
    if (i == 0) rowptr[n] = E;
}

__global__ void scatter_k(const int* __restrict__ src, const int* __restrict__ dst,
                          int* __restrict__ cursor, int* __restrict__ csrc, int E) {
    int e = blockIdx.x * blockDim.x + threadIdx.x;
    if (e >= E) return;
    int pos = atomicAdd(&cursor[dst[e]], 1);
    csrc[pos] = src[e];
}

// ---------------- TF32 tensor-core GEMM -------------------------------------
#define AS_STRIDE 36
#define BS_STRIDE 132
#define AS_FLOATS (128 * AS_STRIDE)

__global__ __launch_bounds__(256) void gemm_tf32(
    const float* __restrict__ A, const float* __restrict__ B,
    const float* __restrict__ bias, float* __restrict__ C,
    int M, int N, int K, int act) {
    __shared__ float smem[AS_FLOATS + 32 * BS_STRIDE];  // ~35 KB
    float* As = smem;                 // [128][36]
    float* Bs = smem + AS_FLOATS;     // [32][132]

    int tid = threadIdx.x;
    int lane = tid & 31;
    int wid = tid >> 5;
    int wr = wid >> 1;   // 0..3
    int wc = wid & 1;    // 0..1
    int rowBase = blockIdx.y * 128, colBase = blockIdx.x * 128;

    wmma::fragment<wmma::accumulator, 16, 16, 8, float> acc[2][4];
#pragma unroll
    for (int i = 0; i < 2; i++)
#pragma unroll
        for (int j = 0; j < 4; j++) wmma::fill_fragment(acc[i][j], 0.0f);

    for (int k0 = 0; k0 < K; k0 += 32) {
#pragma unroll
        for (int i = 0; i < 4; i++) {
            int f = tid + i * 256;
            int r = f >> 3, kq = f & 7;
            int gr = rowBase + r;
            float4 v = make_float4(0.f, 0.f, 0.f, 0.f);
            if (gr < M) v = *(const float4*)(A + (size_t)gr * K + k0 + kq * 4);
            float* p = As + r * AS_STRIDE + kq * 4;
            p[0] = wmma::__float_to_tf32(v.x);
            p[1] = wmma::__float_to_tf32(v.y);
            p[2] = wmma::__float_to_tf32(v.z);
            p[3] = wmma::__float_to_tf32(v.w);
        }
#pragma unroll
        for (int i = 0; i < 4; i++) {
            int f = tid + i * 256;
            int kk = f >> 5, nq = f & 31;
            float4 v = *(const float4*)(B + (size_t)(k0 + kk) * N + colBase + nq * 4);
            float* p = Bs + kk * BS_STRIDE + nq * 4;
            p[0] = wmma::__float_to_tf32(v.x);
            p[1] = wmma::__float_to_tf32(v.y);
            p[2] = wmma::__float_to_tf32(v.z);
            p[3] = wmma::__float_to_tf32(v.w);
        }
        __syncthreads();
#pragma unroll
        for (int ks = 0; ks < 32; ks += 8) {
            wmma::fragment<wmma::matrix_a, 16, 16, 8, wmma::precision::tf32, wmma::row_major> fa[2];
            wmma::fragment<wmma::matrix_b, 16, 16, 8, wmma::precision::tf32, wmma::row_major> fb[4];
#pragma unroll
            for (int i = 0; i < 2; i++)
                wmma::load_matrix_sync(fa[i], As + (wr * 32 + i * 16) * AS_STRIDE + ks, AS_STRIDE);
#pragma unroll
            for (int j = 0; j < 4; j++)
                wmma::load_matrix_sync(fb[j], Bs + ks * BS_STRIDE + wc * 64 + j * 16, BS_STRIDE);
#pragma unroll
            for (int i = 0; i < 2; i++)
#pragma unroll
                for (int j = 0; j < 4; j++)
                    wmma::mma_sync(acc[i][j], fa[i], fb[j], acc[i][j]);
        }
        __syncthreads();
    }

    float* wepi = smem + wid * 256;
#pragma unroll
    for (int i = 0; i < 2; i++) {
#pragma unroll
        for (int j = 0; j < 4; j++) {
            wmma::store_matrix_sync(wepi, acc[i][j], 16, wmma::mem_row_major);
            __syncwarp();
            int r0 = rowBase + wr * 32 + i * 16;
            int c0 = colBase + wc * 64 + j * 16;
#pragma unroll
            for (int t = lane; t < 256; t += 32) {
                int rr = t >> 4, cc = t & 15;
                int r = r0 + rr;
                if (r < M) {
                    float v = wepi[t];
                    int c = c0 + cc;
                    if (bias) v += bias[c];
                    if (act == 1) v = fmaxf(v, 0.0f);
                    C[(size_t)r * N + c] = v;
                }
            }
            __syncwarp();
        }
    }
}

// ---------------- per-node attention logits: one warp per (node, head) ------
__global__ void alpha_k(const float* __restrict__ h, const float* __restrict__ asrc,
                        const float* __restrict__ adst,
                        float* __restrict__ outs, float* __restrict__ outd,
                        int N, int H, int C) {
    int w = (blockIdx.x * blockDim.x + threadIdx.x) >> 5;
    int lane = threadIdx.x & 31;
    if (w >= N * H) return;
    int hh = w % H;
    const float4* hp = (const float4*)(h + (size_t)w * C);
    const float4* ap = (const float4*)(asrc + hh * C);
    const float4* bp = (const float4*)(adst + hh * C);
    float4 hv = hp[lane], av = ap[lane], bv = bp[lane];
    float s1 = hv.x * av.x + hv.y * av.y + hv.z * av.z + hv.w * av.w;
    float s2 = hv.x * bv.x + hv.y * bv.y + hv.z * bv.z + hv.w * bv.w;
#pragma unroll
    for (int o = 16; o; o >>= 1) {
        s1 += __shfl_down_sync(0xffffffffu, s1, o);
        s2 += __shfl_down_sync(0xffffffffu, s2, o);
    }
    if (lane == 0) { outs[w] = s1; outd[w] = s2; }
}

// ---------------- fused GAT edge phase: one warp per (dst, head) -------------
// CSR gather: softmax (max, sum, normalize) + weighted aggregation + bias + ELU
__device__ __forceinline__ float leaky(float v) { return (v >= 0.0f) ? v : 0.2f * v; }

__global__ __launch_bounds__(256) void gat_agg_k(
    const int* __restrict__ rowptr, const int* __restrict__ csrc,
    const float* __restrict__ as, const float* __restrict__ ad,
    const float* __restrict__ hfeat, const float* __restrict__ bias,
    float* __restrict__ out, int N, int H) {
    int w = (blockIdx.x * blockDim.x + threadIdx.x) >> 5;
    int lane = threadIdx.x & 31;
    if (w >= N * H) return;
    int d = w / H, hh = w - d * H;
    int r0 = rowptr[d], r1 = rowptr[d + 1];
    float adv = ad[d * H + hh];
    float self_logit = leaky(as[d * H + hh] + adv);

    // pass A: max over edges + self loop
    float m = self_logit;
    for (int j = r0 + lane; j < r1; j += 32) {
        int s = csrc[j];
        m = fmaxf(m, leaky(as[s * H + hh] + adv));
    }
#pragma unroll
    for (int o = 16; o; o >>= 1) m = fmaxf(m, __shfl_xor_sync(0xffffffffu, m, o));

    // pass B: sum of exp (self counted once, by lane 0)
    float S = (lane == 0) ? __expf(self_logit - m) : 0.0f;
    for (int j = r0 + lane; j < r1; j += 32) {
        int s = csrc[j];
        S += __expf(leaky(as[s * H + hh] + adv) - m);
    }
#pragma unroll
    for (int o = 16; o; o >>= 1) S += __shfl_xor_sync(0xffffffffu, S, o);
    float inv = 1.0f / (S + 1e-16f);

    // pass C: serial over edges, lanes own 4 channels each (C=128)
    float alpha_self = __expf(self_logit - m) * inv;
    const float4* dp = (const float4*)(hfeat + ((size_t)d * H + hh) * 128);
    float4 v = dp[lane];
    float4 acc = make_float4(v.x * alpha_self, v.y * alpha_self,
                             v.z * alpha_self, v.w * alpha_self);
    int j = r0;
    for (; j + 1 < r1; j += 2) {
        int s0 = csrc[j], s1 = csrc[j + 1];
        float a0 = __expf(leaky(as[s0 * H + hh] + adv) - m) * inv;
        float a1 = __expf(leaky(as[s1 * H + hh] + adv) - m) * inv;
        float4 u0 = ((const float4*)(hfeat + ((size_t)s0 * H + hh) * 128))[lane];
        float4 u1 = ((const float4*)(hfeat + ((size_t)s1 * H + hh) * 128))[lane];
        acc.x = fmaf(u0.x, a0, acc.x); acc.y = fmaf(u0.y, a0, acc.y);
        acc.z = fmaf(u0.z, a0, acc.z); acc.w = fmaf(u0.w, a0, acc.w);
        acc.x = fmaf(u1.x, a1, acc.x); acc.y = fmaf(u1.y, a1, acc.y);
        acc.z = fmaf(u1.z, a1, acc.z); acc.w = fmaf(u1.w, a1, acc.w);
    }
    if (j < r1) {
        int s0 = csrc[j];
        float a0 = __expf(leaky(as[s0 * H + hh] + adv) - m) * inv;
        float4 u0 = ((const float4*)(hfeat + ((size_t)s0 * H + hh) * 128))[lane];
        acc.x = fmaf(u0.x, a0, acc.x); acc.y = fmaf(u0.y, a0, acc.y);
        acc.z = fmaf(u0.z, a0, acc.z); acc.w = fmaf(u0.w, a0, acc.w);
    }

    // epilogue: bias + ELU, single store
    const float4 b4 = *(const float4*)(bias + hh * 128 + lane * 4);
    float4 o;
    o.x = acc.x + b4.x; o.x = (o.x > 0.f) ? o.x : expm1f(o.x);
    o.y = acc.y + b4.y; o.y = (o.y > 0.f) ? o.y : expm1f(o.y);
    o.z = acc.z + b4.z; o.z = (o.z > 0.f) ? o.z : expm1f(o.z);
    o.w = acc.w + b4.w; o.w = (o.w > 0.f) ? o.w : expm1f(o.w);
    ((float4*)(out + ((size_t)d * H + hh) * 128))[lane] = o;
}

// ---------------- pooling + final linear ------------------------------------
__global__ void pool_k(const float* __restrict__ x, float* __restrict__ g, int N) {
    int c = threadIdx.x;  // 128
    float acc = 0.0f;
    for (int r = blockIdx.x; r < N; r += gridDim.x) acc += x[(size_t)r * 128 + c];
    atomicAdd(&g[c], acc);
}

__global__ void final_k(const float* __restrict__ g, const float* __restrict__ W,
                        const float* __restrict__ b, float* __restrict__ out,
                        int N, int K, int Nout) {
    __shared__ float gs[128];
    int t = threadIdx.x;  // 256
    if (t < K) gs[t] = g[t] / (float)N;
    __syncthreads();
    if (t < Nout) {
        float acc = b[t];
        for (int k = 0; k < K; k++) acc = fmaf(gs[k], W[k * Nout + t], acc);
        out[t] = acc;
    }
}

// ---------------- launch ------------------------------------------------------
static inline int cdiv(int a, int b) { return (a + b - 1) / b; }

extern "C" void kernel_launch(void* const* d_in, const int* in_sizes, int n_in,
                              void* d_out, int out_size) {
    const float* x     = (const float*)d_in[0];
    const int*   ei    = (const int*)d_in[1];
    const float* W_emb = (const float*)d_in[2];
    const float* b_emb = (const float*)d_in[3];
    const float* W1    = (const float*)d_in[4];
    const float* a1s   = (const float*)d_in[5];
    const float* a1d   = (const float*)d_in[6];
    const float* b1    = (const float*)d_in[7];
    const float* W2    = (const float*)d_in[8];
    const float* a2s   = (const float*)d_in[9];
    const float* a2d   = (const float*)d_in[10];
    const float* b2    = (const float*)d_in[11];
    const float* Wout  = (const float*)d_in[12];
    const float* bout  = (const float*)d_in[13];
    float* out = (float*)d_out;

    const int N = in_sizes[0] / 64;   // 25000
    const int E = in_sizes[1] / 2;    // 400000
    const int H1 = 4, C = 128, F1 = 512, OUTD = 256;
    const int* src = ei;
    const int* dst = ei + E;

    float *p_h0, *p_h1, *p_o1, *p_h2, *p_o2;
    float *p_as1, *p_ad1, *p_as2, *p_ad2, *p_pool;
    int *p_deg, *p_excl, *p_rowptr, *p_cursor, *p_csrc, *p_bsums;
    cudaGetSymbolAddress((void**)&p_h0, g_h0);
    cudaGetSymbolAddress((void**)&p_h1, g_h1);
    cudaGetSymbolAddress((void**)&p_o1, g_o1);
    cudaGetSymbolAddress((void**)&p_h2, g_h2);
    cudaGetSymbolAddress((void**)&p_o2, g_o2);
    cudaGetSymbolAddress((void**)&p_as1, g_as1);
    cudaGetSymbolAddress((void**)&p_ad1, g_ad1);
    cudaGetSymbolAddress((void**)&p_as2, g_as2);
    cudaGetSymbolAddress((void**)&p_ad2, g_ad2);
    cudaGetSymbolAddress((void**)&p_pool, g_pool);
    cudaGetSymbolAddress((void**)&p_deg, g_deg);
    cudaGetSymbolAddress((void**)&p_excl, g_excl);
    cudaGetSymbolAddress((void**)&p_rowptr, g_rowptr);
    cudaGetSymbolAddress((void**)&p_cursor, g_cursor);
    cudaGetSymbolAddress((void**)&p_csrc, g_csrc);
    cudaGetSymbolAddress((void**)&p_bsums, g_bsums);

    const int TB = 256;
    const int NB1024 = cdiv(N, 1024);

    // ---- CSR build (by dst) ----
    cudaMemsetAsync(p_deg, 0, (size_t)N * sizeof(int));
    cudaMemsetAsync(p_pool, 0, 128 * sizeof(float));
    hist_k<<<cdiv(E, TB), TB>>>(dst, p_deg, E);
    scan1_k<<<NB1024, 1024>>>(p_deg, p_excl, p_bsums, N);
    scan2_k<<<1, 32>>>(p_bsums, NB1024);
    scan3_k<<<cdiv(N + 1, TB), TB>>>(p_excl, p_bsums, p_rowptr, p_cursor, N, E);
    scatter_k<<<cdiv(E, TB), TB>>>(src, dst, p_cursor, p_csrc, E);

    // ---- embed: h0 = relu(x @ W_emb + b_emb)  [N,128] ----
    {
        dim3 grid(1, cdiv(N, 128));
        gemm_tf32<<<grid, 256>>>(x, W_emb, b_emb, p_h0, N, 128, 64, 1);
    }

    // ---- GAT layer 1 ----
    {
        dim3 grid(cdiv(F1, 128), cdiv(N, 128));
        gemm_tf32<<<grid, 256>>>(p_h0, W1, nullptr, p_h1, N, F1, 128, 0);
    }
    alpha_k<<<cdiv(N * H1 * 32, TB), TB>>>(p_h1, a1s, a1d, p_as1, p_ad1, N, H1, C);
    gat_agg_k<<<cdiv(N * H1 * 32, TB), TB>>>(p_rowptr, p_csrc, p_as1, p_ad1,
                                             p_h1, b1, p_o1, N, H1);

    // ---- GAT layer 2 (heads=1) ----
    {
        dim3 grid(1, cdiv(N, 128));
        gemm_tf32<<<grid, 256>>>(p_o1, W2, nullptr, p_h2, N, C, F1, 0);
    }
    alpha_k<<<cdiv(N * 32, TB), TB>>>(p_h2, a2s, a2d, p_as2, p_ad2, N, 1, C);
    gat_agg_k<<<cdiv(N * 32, TB), TB>>>(p_rowptr, p_csrc, p_as2, p_ad2,
                                        p_h2, b2, p_o2, N, 1);

    // ---- global mean pool + output linear ----
    pool_k<<<200, 128>>>(p_o2, p_pool, N);
    final_k<<<1, 256>>>(p_pool, Wout, bout, out, N, C, OUTD);
}